// round 3
// baseline (speedup 1.0000x reference)
#include <cuda_runtime.h>
#include <cuda_bf16.h>
#include <cstdint>

#define TOK   256
#define INF   4096
#define OUTF  4096
#define NOUT  32

#define BM 128
#define BN 64
#define BK 128
#define NCH (INF / BK)   // 32 k-chunks of 128 int8

// ---------------- scratch (no cudaMalloc allowed) ----------------
__device__ float   g_mask[INF];
__device__ int8_t  g_xq[TOK * INF];   // rowwise-quantized x, int8
__device__ float   g_xs[TOK];         // rowwise absmax scales

__device__ __forceinline__ uint32_t smem_to_u32(const void* p) {
    uint32_t a;
    asm("{ .reg .u64 t; cvta.to.shared.u64 t, %1; cvt.u32.u64 %0, t; }" : "=r"(a) : "l"(p));
    return a;
}

// ---------------- kernel 1/2: mask build ----------------
__global__ void mask_init_kernel() {
    g_mask[blockIdx.x * 256 + threadIdx.x] = 1.0f;
}
__global__ void mask_scatter_kernel(const int* __restrict__ oidx) {
    g_mask[oidx[threadIdx.x]] = 0.0f;
}

// ---------------- kernel 3: rowwise quantize -> int8 ----------------
__global__ __launch_bounds__(256) void quantize_kernel(const float* __restrict__ x) {
    const int r = blockIdx.x;
    const int tid = threadIdx.x;
    const int wid = tid >> 5, lid = tid & 31;
    __shared__ float red[8];
    __shared__ float s_scale;

    const float4* xr = (const float4*)(x + (size_t)r * INF);
    const float4* mr = (const float4*)g_mask;

    float4 v[4];
    float mx = 0.0f;
#pragma unroll
    for (int t = 0; t < 4; t++) {
        int i = tid * 4 + t;                 // thread covers elems [tid*16, tid*16+15]
        float4 xv = xr[i], mv = mr[i];
        v[t].x = xv.x * mv.x; v[t].y = xv.y * mv.y;
        v[t].z = xv.z * mv.z; v[t].w = xv.w * mv.w;
        mx = fmaxf(mx, fmaxf(fmaxf(fabsf(v[t].x), fabsf(v[t].y)),
                             fmaxf(fabsf(v[t].z), fabsf(v[t].w))));
    }
#pragma unroll
    for (int d = 16; d > 0; d >>= 1) mx = fmaxf(mx, __shfl_xor_sync(0xFFFFFFFFu, mx, d));
    if (lid == 0) red[wid] = mx;
    __syncthreads();
    if (tid == 0) {
        float m = red[0];
#pragma unroll
        for (int i = 1; i < 8; i++) m = fmaxf(m, red[i]);
        s_scale = m;
        g_xs[r] = m;
    }
    __syncthreads();
    const float r127 = 127.0f / fmaxf(s_scale, 1e-8f);

    uint32_t pk[4];
#pragma unroll
    for (int t = 0; t < 4; t++) {
        int q0 = min(max(__float2int_rn(v[t].x * r127), -127), 127);
        int q1 = min(max(__float2int_rn(v[t].y * r127), -127), 127);
        int q2 = min(max(__float2int_rn(v[t].z * r127), -127), 127);
        int q3 = min(max(__float2int_rn(v[t].w * r127), -127), 127);
        uint32_t p0 = __byte_perm((uint32_t)q0, (uint32_t)q1, 0x0040);
        uint32_t p1 = __byte_perm((uint32_t)q2, (uint32_t)q3, 0x0040);
        pk[t] = __byte_perm(p0, p1, 0x5410);
    }
    *(uint4*)(g_xq + (size_t)r * INF + tid * 16) = make_uint4(pk[0], pk[1], pk[2], pk[3]);
}

// ---------------- kernel 4: outlier GEMM + bias -> out ----------------
// out[t,o] = bias[o] + sum_j x[t, oidx[j]] * ow[o, j]
// grid (32, 4): o-tile 128, t-tile 64; 256 threads.
__global__ __launch_bounds__(256) void outlier_bias_kernel(const float* __restrict__ x,
                                                           const int* __restrict__ oidx,
                                                           const float* __restrict__ ow,
                                                           const float* __restrict__ bias,
                                                           float* __restrict__ out) {
    __shared__ float s_owT[NOUT * 128];  // [j][o] transposed, 16KB
    __shared__ float s_x[64 * NOUT];     // [t][j], 8KB
    __shared__ float s_b[128];
    __shared__ int   s_oi[NOUT];

    const int tid = threadIdx.x;
    const int obase = blockIdx.x * 128;
    const int tbase = blockIdx.y * 64;

    if (tid < NOUT) s_oi[tid] = oidx[tid];
    if (tid < 128)  s_b[tid] = bias[obase + tid];
    __syncthreads();

    // ow tile [128 o][32 j] -> transposed smem
#pragma unroll
    for (int t = 0; t < 4; t++) {
        int i = tid + t * 256;               // i in [0,1024): float4 index
        int o = i >> 3, j4 = i & 7;
        float4 f = ((const float4*)ow)[(size_t)obase * 8 + i];
        s_owT[(j4 * 4 + 0) * 128 + o] = f.x;
        s_owT[(j4 * 4 + 1) * 128 + o] = f.y;
        s_owT[(j4 * 4 + 2) * 128 + o] = f.z;
        s_owT[(j4 * 4 + 3) * 128 + o] = f.w;
    }
    // x outlier gather [64 t][32 j]
#pragma unroll
    for (int t = 0; t < 8; t++) {
        int i = tid + t * 256;               // i in [0,2048)
        int r = i >> 5, j = i & 31;
        s_x[i] = x[(size_t)(tbase + r) * INF + s_oi[j]];
    }
    __syncthreads();

    const int ty = tid >> 5, tx = tid & 31;  // thread -> 8 t-rows x 4 o-cols
    float acc[8][4];
#pragma unroll
    for (int tt = 0; tt < 8; tt++)
#pragma unroll
        for (int c = 0; c < 4; c++) acc[tt][c] = s_b[tx + c * 32];

#pragma unroll
    for (int j = 0; j < NOUT; j++) {
        float wv[4];
#pragma unroll
        for (int c = 0; c < 4; c++) wv[c] = s_owT[j * 128 + tx + c * 32];
#pragma unroll
        for (int tt = 0; tt < 8; tt++) {
            float xv = s_x[(ty * 8 + tt) * NOUT + j];
#pragma unroll
            for (int c = 0; c < 4; c++) acc[tt][c] += xv * wv[c];
        }
    }
#pragma unroll
    for (int tt = 0; tt < 8; tt++)
#pragma unroll
        for (int c = 0; c < 4; c++)
            out[(size_t)(tbase + ty * 8 + tt) * OUTF + obase + tx + c * 32] = acc[tt][c];
}

// ---------------- kernel 5: int8 tensor-core GEMM + epilogue ----------------
// CTA 128x64, 4 warps (2m x 2n), warp tile 64x32, mma m16n8k32 s8.
// smem layout (dynamic, 48KB exactly): A stages @0/@16384 (128x128B each),
// B stages @32768/@40960 (64x128B each). SW128 swizzle on all 128B rows.
#define SA_OFF(s) ((s) * 16384)
#define SB_OFF(s) (32768 + (s) * 8192)

__global__ __launch_bounds__(128, 1) void gemm_kernel(const int* __restrict__ w,
                                                      const float* __restrict__ wscale,
                                                      float* __restrict__ out) {
    extern __shared__ char smem[];
    const uint32_t sb = smem_to_u32(smem);
    const int tid = threadIdx.x;
    const int lane = tid & 31, wid = tid >> 5;
    const int wm = wid >> 1, wn = wid & 1;
    const int nbase = blockIdx.x * BN;
    const int mbase = blockIdx.y * BM;

    const int8_t* abase = g_xq + (size_t)mbase * INF;
    const int*    bbase = w + (size_t)nbase * INF;

    int acc[4][4][4];
#pragma unroll
    for (int i = 0; i < 4; i++)
#pragma unroll
        for (int j = 0; j < 4; j++)
#pragma unroll
            for (int k = 0; k < 4; k++) acc[i][j][k] = 0;

    int4 breg[16];

    // ---- staging helpers ----
    // A: 8 cp.async x 16B per thread; B: 16 LDG.128 int32 -> pack -> 16 STS.32
    auto issueA = [&](int c, int s) {
#pragma unroll
        for (int t = 0; t < 8; t++) {
            int i = tid + t * 128;
            int r = i >> 3, cc = i & 7;
            const int8_t* src = abase + (size_t)r * INF + c * BK + cc * 16;
            uint32_t dst = sb + SA_OFF(s) + (uint32_t)(r * 128 + (((cc ^ (r & 7))) << 4));
            asm volatile("cp.async.cg.shared.global [%0], [%1], 16;" :: "r"(dst), "l"(src));
        }
        asm volatile("cp.async.commit_group;" ::: "memory");
    };
    auto issueB = [&](int c) {
#pragma unroll
        for (int t = 0; t < 16; t++) {
            int i = tid + t * 128;
            int r = i >> 5, c4 = i & 31;
            breg[t] = *(const int4*)(bbase + (size_t)r * INF + c * BK + c4 * 4);
        }
    };
    auto storeB = [&](int s) {
#pragma unroll
        for (int t = 0; t < 16; t++) {
            int i = tid + t * 128;
            int r = i >> 5, c4 = i & 31;
            uint32_t p0 = __byte_perm((uint32_t)breg[t].x, (uint32_t)breg[t].y, 0x0040);
            uint32_t p1 = __byte_perm((uint32_t)breg[t].z, (uint32_t)breg[t].w, 0x0040);
            uint32_t pk = __byte_perm(p0, p1, 0x5410);
            uint32_t off = (uint32_t)(r * 128 + c4 * 4);
            off ^= ((uint32_t)(r & 7)) << 4;   // SW128 swizzle (16B-chunk XOR)
            *(uint32_t*)(smem + SB_OFF(s) + off) = pk;
        }
    };
    auto compute = [&](int s) {
#pragma unroll
        for (int ksl = 0; ksl < 4; ksl++) {
            uint32_t a[4][4];
#pragma unroll
            for (int mf = 0; mf < 4; mf++) {
                int row = wm * 64 + mf * 16 + (lane & 15);
                int kc = 2 * ksl + (lane >> 4);
                uint32_t ad = sb + SA_OFF(s) +
                              (uint32_t)(row * 128 + ((kc ^ (row & 7)) << 4));
                asm volatile("ldmatrix.sync.aligned.m8n8.x4.shared.b16 {%0,%1,%2,%3}, [%4];"
                    : "=r"(a[mf][0]), "=r"(a[mf][1]), "=r"(a[mf][2]), "=r"(a[mf][3])
                    : "r"(ad));
            }
            uint32_t b[2][4];
#pragma unroll
            for (int np = 0; np < 2; np++) {
                int n = wn * 32 + np * 16 + (lane & 7) + ((lane >> 4) << 3);
                int kc = 2 * ksl + ((lane >> 3) & 1);
                uint32_t bd = sb + SB_OFF(s) +
                              (uint32_t)(n * 128 + ((kc ^ (n & 7)) << 4));
                asm volatile("ldmatrix.sync.aligned.m8n8.x4.shared.b16 {%0,%1,%2,%3}, [%4];"
                    : "=r"(b[np][0]), "=r"(b[np][1]), "=r"(b[np][2]), "=r"(b[np][3])
                    : "r"(bd));
            }
#pragma unroll
            for (int mf = 0; mf < 4; mf++)
#pragma unroll
                for (int nf = 0; nf < 4; nf++) {
                    uint32_t b0 = b[nf >> 1][(nf & 1) * 2];
                    uint32_t b1 = b[nf >> 1][(nf & 1) * 2 + 1];
                    asm volatile(
                        "mma.sync.aligned.m16n8k32.row.col.s32.s8.s8.s32 "
                        "{%0,%1,%2,%3}, {%4,%5,%6,%7}, {%8,%9}, {%0,%1,%2,%3};"
                        : "+r"(acc[mf][nf][0]), "+r"(acc[mf][nf][1]),
                          "+r"(acc[mf][nf][2]), "+r"(acc[mf][nf][3])
                        : "r"(a[mf][0]), "r"(a[mf][1]), "r"(a[mf][2]), "r"(a[mf][3]),
                          "r"(b0), "r"(b1));
                }
        }
    };

    // ---- prologue ----
    issueA(0, 0);
    issueB(0);
    storeB(0);
    asm volatile("cp.async.wait_group 0;" ::: "memory");
    __syncthreads();

    // ---- main loop: double-buffered, loads-in-flight over compute ----
#pragma unroll 1
    for (int c = 0; c < NCH; c++) {
        const int s = c & 1;
        if (c + 1 < NCH) {
            issueA(c + 1, 1 - s);
            issueB(c + 1);
        }
        compute(s);
        if (c + 1 < NCH) {
            storeB(1 - s);
            asm volatile("cp.async.wait_group 0;" ::: "memory");
        }
        __syncthreads();
    }

    // ---- epilogue: out = s32*(xs*ws/127^2) + out_prev(outlier+bias) ----
    const float inv = 1.0f / 16129.0f;
    const int grp = lane >> 2, qid = lane & 3;
#pragma unroll
    for (int mf = 0; mf < 4; mf++) {
        const int m0 = mbase + wm * 64 + mf * 16 + grp;
        const float s0 = g_xs[m0] * inv;
        const float s1 = g_xs[m0 + 8] * inv;
#pragma unroll
        for (int nf = 0; nf < 4; nf++) {
            const int o = nbase + wn * 32 + nf * 8 + qid * 2;
            const float2 wsv = *(const float2*)(wscale + o);
            float2 p0 = *(float2*)(out + (size_t)m0 * OUTF + o);
            float2 p1 = *(float2*)(out + (size_t)(m0 + 8) * OUTF + o);
            float2 r0, r1;
            r0.x = (float)acc[mf][nf][0] * (s0 * wsv.x) + p0.x;
            r0.y = (float)acc[mf][nf][1] * (s0 * wsv.y) + p0.y;
            r1.x = (float)acc[mf][nf][2] * (s1 * wsv.x) + p1.x;
            r1.y = (float)acc[mf][nf][3] * (s1 * wsv.y) + p1.y;
            *(float2*)(out + (size_t)m0 * OUTF + o) = r0;
            *(float2*)(out + (size_t)(m0 + 8) * OUTF + o) = r1;
        }
    }
}

// ---------------- launch ----------------
extern "C" void kernel_launch(void* const* d_in, const int* in_sizes, int n_in,
                              void* d_out, int out_size) {
    const float* x    = (const float*)d_in[0];
    const int*   w    = (const int*)d_in[1];
    const float* ws   = (const float*)d_in[2];
    const int*   oidx = (const int*)d_in[3];
    const float* ow   = (const float*)d_in[4];
    const float* bias = (const float*)d_in[5];
    float* out = (float*)d_out;

    mask_init_kernel<<<INF / 256, 256>>>();
    mask_scatter_kernel<<<1, NOUT>>>(oidx);
    quantize_kernel<<<TOK, 256>>>(x);
    outlier_bias_kernel<<<dim3(OUTF / 128, TOK / 64), 256>>>(x, oidx, ow, bias, out);
    gemm_kernel<<<dim3(OUTF / BN, TOK / BM), 128, 49152>>>(w, ws, out);
}

// round 4
// speedup vs baseline: 1.1180x; 1.1180x over previous
#include <cuda_runtime.h>
#include <cuda_bf16.h>
#include <cstdint>

#define TOK   256
#define INF   4096
#define OUTF  4096
#define NOUT  32

#define BM 128
#define BN 64
#define BK 128
#define NCH (INF / BK)   // 32 k-chunks of 128 int8
#define STAGES 4

// ---------------- scratch (no cudaMalloc allowed) ----------------
__device__ float   g_mask[INF];
__device__ int8_t  g_xq[TOK * INF];    // rowwise-quantized x, int8
__device__ float   g_xs[TOK];          // rowwise absmax scales
__device__ float   g_xout[TOK * NOUT]; // gathered outlier columns
__device__ int8_t  g_w8[(size_t)OUTF * INF]; // prepacked int8 weights (16MB)

__device__ __forceinline__ uint32_t smem_to_u32(const void* p) {
    uint32_t a;
    asm("{ .reg .u64 t; cvta.to.shared.u64 t, %1; cvt.u32.u64 %0, t; }" : "=r"(a) : "l"(p));
    return a;
}

// ---------------- mask build ----------------
__global__ void mask_init_kernel() {
    g_mask[blockIdx.x * 256 + threadIdx.x] = 1.0f;
}
__global__ void mask_scatter_kernel(const int* __restrict__ oidx) {
    g_mask[oidx[threadIdx.x]] = 0.0f;
}

// ---------------- prepack: w int32 -> int8 ----------------
// 16M elements; 256 thr x 8 elems = 2048/CTA -> 8192 CTAs. Pure streaming.
__global__ __launch_bounds__(256) void pack_w_kernel(const int* __restrict__ w) {
    const size_t i = ((size_t)blockIdx.x * 2048) + (size_t)threadIdx.x * 8;
    int4 v0 = *(const int4*)(w + i);
    int4 v1 = *(const int4*)(w + i + 4);
    uint32_t p0 = __byte_perm((uint32_t)v0.x, (uint32_t)v0.y, 0x0040);
    uint32_t p1 = __byte_perm((uint32_t)v0.z, (uint32_t)v0.w, 0x0040);
    uint32_t p2 = __byte_perm((uint32_t)v1.x, (uint32_t)v1.y, 0x0040);
    uint32_t p3 = __byte_perm((uint32_t)v1.z, (uint32_t)v1.w, 0x0040);
    uint2 pk;
    pk.x = __byte_perm(p0, p1, 0x5410);
    pk.y = __byte_perm(p2, p3, 0x5410);
    *(uint2*)(g_w8 + i) = pk;
}

// ---------------- rowwise quantize -> int8 (+ outlier gather) ----------------
__global__ __launch_bounds__(256) void quantize_kernel(const float* __restrict__ x,
                                                       const int* __restrict__ oidx) {
    const int r = blockIdx.x;
    const int tid = threadIdx.x;
    const int wid = tid >> 5, lid = tid & 31;
    __shared__ float red[8];
    __shared__ float s_scale;

    const float4* xr = (const float4*)(x + (size_t)r * INF);
    const float4* mr = (const float4*)g_mask;

    float4 v[4];
    float mx = 0.0f;
#pragma unroll
    for (int t = 0; t < 4; t++) {
        int i = tid * 4 + t;
        float4 xv = xr[i], mv = mr[i];
        v[t].x = xv.x * mv.x; v[t].y = xv.y * mv.y;
        v[t].z = xv.z * mv.z; v[t].w = xv.w * mv.w;
        mx = fmaxf(mx, fmaxf(fmaxf(fabsf(v[t].x), fabsf(v[t].y)),
                             fmaxf(fabsf(v[t].z), fabsf(v[t].w))));
    }
#pragma unroll
    for (int d = 16; d > 0; d >>= 1) mx = fmaxf(mx, __shfl_xor_sync(0xFFFFFFFFu, mx, d));
    if (lid == 0) red[wid] = mx;
    __syncthreads();
    if (tid == 0) {
        float m = red[0];
#pragma unroll
        for (int i = 1; i < 8; i++) m = fmaxf(m, red[i]);
        s_scale = m;
        g_xs[r] = m;
    }
    __syncthreads();
    const float r127 = 127.0f / fmaxf(s_scale, 1e-8f);

    uint32_t pk[4];
#pragma unroll
    for (int t = 0; t < 4; t++) {
        int q0 = min(max(__float2int_rn(v[t].x * r127), -127), 127);
        int q1 = min(max(__float2int_rn(v[t].y * r127), -127), 127);
        int q2 = min(max(__float2int_rn(v[t].z * r127), -127), 127);
        int q3 = min(max(__float2int_rn(v[t].w * r127), -127), 127);
        uint32_t p0 = __byte_perm((uint32_t)q0, (uint32_t)q1, 0x0040);
        uint32_t p1 = __byte_perm((uint32_t)q2, (uint32_t)q3, 0x0040);
        pk[t] = __byte_perm(p0, p1, 0x5410);
    }
    *(uint4*)(g_xq + (size_t)r * INF + tid * 16) = make_uint4(pk[0], pk[1], pk[2], pk[3]);

    if (tid < NOUT) {
        g_xout[r * NOUT + tid] = x[(size_t)r * INF + oidx[tid]];
    }
}

// ---------------- outlier GEMM + bias -> out ----------------
// out[t,o] = bias[o] + sum_j g_xout[t,j] * ow[o,j];  grid (32 o-tiles, 4 t-tiles)
__global__ __launch_bounds__(256) void outlier_bias_kernel(const float* __restrict__ ow,
                                                           const float* __restrict__ bias,
                                                           float* __restrict__ out) {
    __shared__ float s_owT[NOUT * 128];  // [j][o]
    __shared__ float s_x[64 * NOUT];     // [t][j]
    __shared__ float s_b[128];

    const int tid = threadIdx.x;
    const int obase = blockIdx.x * 128;
    const int tbase = blockIdx.y * 64;

    if (tid < 128) s_b[tid] = bias[obase + tid];

#pragma unroll
    for (int t = 0; t < 4; t++) {
        int i = tid + t * 256;               // float4 index in [0,1024)
        int o = i >> 3, j4 = i & 7;
        float4 f = ((const float4*)ow)[(size_t)obase * 8 + i];
        s_owT[(j4 * 4 + 0) * 128 + o] = f.x;
        s_owT[(j4 * 4 + 1) * 128 + o] = f.y;
        s_owT[(j4 * 4 + 2) * 128 + o] = f.z;
        s_owT[(j4 * 4 + 3) * 128 + o] = f.w;
    }
    // coalesced copy of 64x32 floats from g_xout
#pragma unroll
    for (int t = 0; t < 2; t++) {
        int i = tid + t * 256;               // float4 index in [0,512)
        ((float4*)s_x)[i] = ((const float4*)(g_xout + tbase * NOUT))[i];
    }
    __syncthreads();

    const int ty = tid >> 5, tx = tid & 31;
    float acc[8][4];
#pragma unroll
    for (int tt = 0; tt < 8; tt++)
#pragma unroll
        for (int c = 0; c < 4; c++) acc[tt][c] = s_b[tx + c * 32];

#pragma unroll
    for (int j = 0; j < NOUT; j++) {
        float wv[4];
#pragma unroll
        for (int c = 0; c < 4; c++) wv[c] = s_owT[j * 128 + tx + c * 32];
#pragma unroll
        for (int tt = 0; tt < 8; tt++) {
            float xv = s_x[(ty * 8 + tt) * NOUT + j];
#pragma unroll
            for (int c = 0; c < 4; c++) acc[tt][c] += xv * wv[c];
        }
    }
#pragma unroll
    for (int tt = 0; tt < 8; tt++)
#pragma unroll
        for (int c = 0; c < 4; c++)
            out[(size_t)(tbase + ty * 8 + tt) * OUTF + obase + tx + c * 32] = acc[tt][c];
}

// ---------------- int8 tensor-core GEMM + epilogue ----------------
// CTA 128x64, 8 warps (4m x 2n), warp tile 32x32, mma m16n8k32 s8.
// 4-stage cp.async pipeline. smem: A stages 4x16KB @0, B stages 4x8KB @65536.
#define SA_OFF(s) ((s) * 16384)
#define SB_OFF(s) (65536 + (s) * 8192)
#define SMEM_TOTAL 98304

__global__ __launch_bounds__(256, 1) void gemm_kernel(const float* __restrict__ wscale,
                                                      float* __restrict__ out) {
    extern __shared__ char smem[];
    const uint32_t sb = smem_to_u32(smem);
    const int tid = threadIdx.x;
    const int lane = tid & 31, wid = tid >> 5;
    const int wm = wid >> 1, wn = wid & 1;    // 4m x 2n
    const int nbase = blockIdx.x * BN;
    const int mbase = blockIdx.y * BM;

    const int8_t* abase = g_xq + (size_t)mbase * INF;
    const int8_t* bbase = g_w8 + (size_t)nbase * INF;

    int acc[2][4][4];
#pragma unroll
    for (int i = 0; i < 2; i++)
#pragma unroll
        for (int j = 0; j < 4; j++)
#pragma unroll
            for (int k = 0; k < 4; k++) acc[i][j][k] = 0;

    auto issue = [&](int c, int s) {
        // A: 128 rows x 128B = 1024 16B-chunks / 256 thr = 4
#pragma unroll
        for (int t = 0; t < 4; t++) {
            int i = tid + t * 256;
            int r = i >> 3, cc = i & 7;
            const int8_t* src = abase + (size_t)r * INF + c * BK + cc * 16;
            uint32_t dst = sb + SA_OFF(s) + (uint32_t)(r * 128 + ((cc ^ (r & 7)) << 4));
            asm volatile("cp.async.cg.shared.global [%0], [%1], 16;" :: "r"(dst), "l"(src));
        }
        // B: 64 rows x 128B = 512 chunks / 256 thr = 2
#pragma unroll
        for (int t = 0; t < 2; t++) {
            int i = tid + t * 256;
            int r = i >> 3, cc = i & 7;
            const int8_t* src = bbase + (size_t)r * INF + c * BK + cc * 16;
            uint32_t dst = sb + SB_OFF(s) + (uint32_t)(r * 128 + ((cc ^ (r & 7)) << 4));
            asm volatile("cp.async.cg.shared.global [%0], [%1], 16;" :: "r"(dst), "l"(src));
        }
        asm volatile("cp.async.commit_group;" ::: "memory");
    };

    auto compute = [&](int s) {
#pragma unroll
        for (int ksl = 0; ksl < 4; ksl++) {
            uint32_t a[2][4];
#pragma unroll
            for (int mf = 0; mf < 2; mf++) {
                int row = wm * 32 + mf * 16 + (lane & 15);
                int kc = 2 * ksl + (lane >> 4);
                uint32_t ad = sb + SA_OFF(s) +
                              (uint32_t)(row * 128 + ((kc ^ (row & 7)) << 4));
                asm volatile("ldmatrix.sync.aligned.m8n8.x4.shared.b16 {%0,%1,%2,%3}, [%4];"
                    : "=r"(a[mf][0]), "=r"(a[mf][1]), "=r"(a[mf][2]), "=r"(a[mf][3])
                    : "r"(ad));
            }
            uint32_t b[2][4];
#pragma unroll
            for (int np = 0; np < 2; np++) {
                int n = wn * 32 + np * 16 + (lane & 7) + ((lane >> 4) << 3);
                int kc = 2 * ksl + ((lane >> 3) & 1);
                uint32_t bd = sb + SB_OFF(s) +
                              (uint32_t)(n * 128 + ((kc ^ (n & 7)) << 4));
                asm volatile("ldmatrix.sync.aligned.m8n8.x4.shared.b16 {%0,%1,%2,%3}, [%4];"
                    : "=r"(b[np][0]), "=r"(b[np][1]), "=r"(b[np][2]), "=r"(b[np][3])
                    : "r"(bd));
            }
#pragma unroll
            for (int mf = 0; mf < 2; mf++)
#pragma unroll
                for (int nf = 0; nf < 4; nf++) {
                    uint32_t b0 = b[nf >> 1][(nf & 1) * 2];
                    uint32_t b1 = b[nf >> 1][(nf & 1) * 2 + 1];
                    asm volatile(
                        "mma.sync.aligned.m16n8k32.row.col.s32.s8.s8.s32 "
                        "{%0,%1,%2,%3}, {%4,%5,%6,%7}, {%8,%9}, {%0,%1,%2,%3};"
                        : "+r"(acc[mf][nf][0]), "+r"(acc[mf][nf][1]),
                          "+r"(acc[mf][nf][2]), "+r"(acc[mf][nf][3])
                        : "r"(a[mf][0]), "r"(a[mf][1]), "r"(a[mf][2]), "r"(a[mf][3]),
                          "r"(b0), "r"(b1));
                }
        }
    };

    // ---- prologue: 3 stages in flight ----
    issue(0, 0);
    issue(1, 1);
    issue(2, 2);

    // ---- main loop ----
#pragma unroll 1
    for (int c = 0; c < NCH; c++) {
        const int s = c & (STAGES - 1);
        asm volatile("cp.async.wait_group 2;" ::: "memory");
        __syncthreads();
        if (c + 3 < NCH) issue(c + 3, (c + 3) & (STAGES - 1));
        compute(s);
    }

    // ---- epilogue: out = s32*(xs*ws/127^2) + out_prev(outlier+bias) ----
    const float inv = 1.0f / 16129.0f;
    const int grp = lane >> 2, qid = lane & 3;
#pragma unroll
    for (int mf = 0; mf < 2; mf++) {
        const int m0 = mbase + wm * 32 + mf * 16 + grp;
        const float s0 = g_xs[m0] * inv;
        const float s1 = g_xs[m0 + 8] * inv;
#pragma unroll
        for (int nf = 0; nf < 4; nf++) {
            const int o = nbase + wn * 32 + nf * 8 + qid * 2;
            const float2 wsv = *(const float2*)(wscale + o);
            float2 p0 = *(float2*)(out + (size_t)m0 * OUTF + o);
            float2 p1 = *(float2*)(out + (size_t)(m0 + 8) * OUTF + o);
            float2 r0, r1;
            r0.x = (float)acc[mf][nf][0] * (s0 * wsv.x) + p0.x;
            r0.y = (float)acc[mf][nf][1] * (s0 * wsv.y) + p0.y;
            r1.x = (float)acc[mf][nf][2] * (s1 * wsv.x) + p1.x;
            r1.y = (float)acc[mf][nf][3] * (s1 * wsv.y) + p1.y;
            *(float2*)(out + (size_t)m0 * OUTF + o) = r0;
            *(float2*)(out + (size_t)(m0 + 8) * OUTF + o) = r1;
        }
    }
}

// ---------------- launch ----------------
extern "C" void kernel_launch(void* const* d_in, const int* in_sizes, int n_in,
                              void* d_out, int out_size) {
    const float* x    = (const float*)d_in[0];
    const int*   w    = (const int*)d_in[1];
    const float* ws   = (const float*)d_in[2];
    const int*   oidx = (const int*)d_in[3];
    const float* ow   = (const float*)d_in[4];
    const float* bias = (const float*)d_in[5];
    float* out = (float*)d_out;

    cudaFuncSetAttribute(gemm_kernel, cudaFuncAttributeMaxDynamicSharedMemorySize, SMEM_TOTAL);

    mask_init_kernel<<<INF / 256, 256>>>();
    mask_scatter_kernel<<<1, NOUT>>>(oidx);
    pack_w_kernel<<<(size_t)OUTF * INF / 2048, 256>>>(w);
    quantize_kernel<<<TOK, 256>>>(x, oidx);
    outlier_bias_kernel<<<dim3(OUTF / 128, TOK / 64), 256>>>(ow, bias, out);
    gemm_kernel<<<dim3(OUTF / BN, TOK / BM), 256, SMEM_TOTAL>>>(ws, out);
}

// round 5
// speedup vs baseline: 1.1658x; 1.0428x over previous
#include <cuda_runtime.h>
#include <cuda_bf16.h>
#include <cstdint>

#define TOK   256
#define INF   4096
#define OUTF  4096
#define NOUT  32

#define BM 128
#define BN 64
#define BK 128
#define KSPLIT 2
#define NCH_PER (INF / BK / KSPLIT)   // 16 k-chunks per CTA
#define STAGES 4

// ---------------- scratch (no cudaMalloc allowed) ----------------
__device__ float   g_mask[INF];
__device__ int8_t  g_xq[TOK * INF];    // rowwise-quantized x, int8
__device__ float   g_xs[TOK];          // rowwise absmax scales
__device__ float   g_xout[TOK * NOUT]; // gathered outlier columns
__device__ int8_t  g_w8[(size_t)OUTF * INF]; // prepacked int8 weights (16MB)

__device__ __forceinline__ uint32_t smem_to_u32(const void* p) {
    uint32_t a;
    asm("{ .reg .u64 t; cvta.to.shared.u64 t, %1; cvt.u32.u64 %0, t; }" : "=r"(a) : "l"(p));
    return a;
}

// ---------------- mask build (2 launches keeps gemm at launch #6 for ncu -s 5) ----
__global__ void mask_init_kernel() {
    g_mask[blockIdx.x * 256 + threadIdx.x] = 1.0f;
}
__global__ void mask_scatter_kernel(const int* __restrict__ oidx) {
    g_mask[oidx[threadIdx.x]] = 0.0f;
}

// ---------------- prepack: w int32 -> int8 (streaming 64MB->16MB) ----------------
__global__ __launch_bounds__(256) void pack_w_kernel(const int* __restrict__ w) {
    const size_t i = ((size_t)blockIdx.x * 2048) + (size_t)threadIdx.x * 8;
    int4 v0 = *(const int4*)(w + i);
    int4 v1 = *(const int4*)(w + i + 4);
    uint32_t p0 = __byte_perm((uint32_t)v0.x, (uint32_t)v0.y, 0x0040);
    uint32_t p1 = __byte_perm((uint32_t)v0.z, (uint32_t)v0.w, 0x0040);
    uint32_t p2 = __byte_perm((uint32_t)v1.x, (uint32_t)v1.y, 0x0040);
    uint32_t p3 = __byte_perm((uint32_t)v1.z, (uint32_t)v1.w, 0x0040);
    uint2 pk;
    pk.x = __byte_perm(p0, p1, 0x5410);
    pk.y = __byte_perm(p2, p3, 0x5410);
    *(uint2*)(g_w8 + i) = pk;
}

// ---------------- rowwise quantize -> int8 (+ outlier gather) ----------------
__global__ __launch_bounds__(256) void quantize_kernel(const float* __restrict__ x,
                                                       const int* __restrict__ oidx) {
    const int r = blockIdx.x;
    const int tid = threadIdx.x;
    const int wid = tid >> 5, lid = tid & 31;
    __shared__ float red[8];
    __shared__ float s_scale;

    const float4* xr = (const float4*)(x + (size_t)r * INF);
    const float4* mr = (const float4*)g_mask;

    float4 v[4];
    float mx = 0.0f;
#pragma unroll
    for (int t = 0; t < 4; t++) {
        int i = tid * 4 + t;
        float4 xv = xr[i], mv = mr[i];
        v[t].x = xv.x * mv.x; v[t].y = xv.y * mv.y;
        v[t].z = xv.z * mv.z; v[t].w = xv.w * mv.w;
        mx = fmaxf(mx, fmaxf(fmaxf(fabsf(v[t].x), fabsf(v[t].y)),
                             fmaxf(fabsf(v[t].z), fabsf(v[t].w))));
    }
#pragma unroll
    for (int d = 16; d > 0; d >>= 1) mx = fmaxf(mx, __shfl_xor_sync(0xFFFFFFFFu, mx, d));
    if (lid == 0) red[wid] = mx;
    __syncthreads();
    if (tid == 0) {
        float m = red[0];
#pragma unroll
        for (int i = 1; i < 8; i++) m = fmaxf(m, red[i]);
        s_scale = m;
        g_xs[r] = m;
    }
    __syncthreads();
    const float r127 = 127.0f / fmaxf(s_scale, 1e-8f);

    uint32_t pk[4];
#pragma unroll
    for (int t = 0; t < 4; t++) {
        int q0 = min(max(__float2int_rn(v[t].x * r127), -127), 127);
        int q1 = min(max(__float2int_rn(v[t].y * r127), -127), 127);
        int q2 = min(max(__float2int_rn(v[t].z * r127), -127), 127);
        int q3 = min(max(__float2int_rn(v[t].w * r127), -127), 127);
        uint32_t p0 = __byte_perm((uint32_t)q0, (uint32_t)q1, 0x0040);
        uint32_t p1 = __byte_perm((uint32_t)q2, (uint32_t)q3, 0x0040);
        pk[t] = __byte_perm(p0, p1, 0x5410);
    }
    *(uint4*)(g_xq + (size_t)r * INF + tid * 16) = make_uint4(pk[0], pk[1], pk[2], pk[3]);

    if (tid < NOUT) {
        g_xout[r * NOUT + tid] = x[(size_t)r * INF + oidx[tid]];
    }
}

// ---------------- outlier GEMM + bias -> out (prefill) ----------------
__global__ __launch_bounds__(256) void outlier_bias_kernel(const float* __restrict__ ow,
                                                           const float* __restrict__ bias,
                                                           float* __restrict__ out) {
    __shared__ float s_owT[NOUT * 128];  // [j][o]
    __shared__ float s_x[64 * NOUT];     // [t][j]
    __shared__ float s_b[128];

    const int tid = threadIdx.x;
    const int obase = blockIdx.x * 128;
    const int tbase = blockIdx.y * 64;

    if (tid < 128) s_b[tid] = bias[obase + tid];

#pragma unroll
    for (int t = 0; t < 4; t++) {
        int i = tid + t * 256;               // float4 index in [0,1024)
        int o = i >> 3, j4 = i & 7;
        float4 f = ((const float4*)ow)[(size_t)obase * 8 + i];
        s_owT[(j4 * 4 + 0) * 128 + o] = f.x;
        s_owT[(j4 * 4 + 1) * 128 + o] = f.y;
        s_owT[(j4 * 4 + 2) * 128 + o] = f.z;
        s_owT[(j4 * 4 + 3) * 128 + o] = f.w;
    }
#pragma unroll
    for (int t = 0; t < 2; t++) {
        int i = tid + t * 256;               // float4 index in [0,512)
        ((float4*)s_x)[i] = ((const float4*)(g_xout + tbase * NOUT))[i];
    }
    __syncthreads();

    const int ty = tid >> 5, tx = tid & 31;
    float acc[8][4];
#pragma unroll
    for (int tt = 0; tt < 8; tt++)
#pragma unroll
        for (int c = 0; c < 4; c++) acc[tt][c] = s_b[tx + c * 32];

#pragma unroll
    for (int j = 0; j < NOUT; j++) {
        float wv[4];
#pragma unroll
        for (int c = 0; c < 4; c++) wv[c] = s_owT[j * 128 + tx + c * 32];
#pragma unroll
        for (int tt = 0; tt < 8; tt++) {
            float xv = s_x[(ty * 8 + tt) * NOUT + j];
#pragma unroll
            for (int c = 0; c < 4; c++) acc[tt][c] += xv * wv[c];
        }
    }
#pragma unroll
    for (int tt = 0; tt < 8; tt++)
#pragma unroll
        for (int c = 0; c < 4; c++)
            out[(size_t)(tbase + ty * 8 + tt) * OUTF + obase + tx + c * 32] = acc[tt][c];
}

// ---------------- int8 tensor-core GEMM, K-split, atomic epilogue ----------------
// CTA 128x64 over K/2; 8 warps (4m x 2n), warp tile 32x32, mma m16n8k32 s8.
// 4-stage cp.async pipeline, 96KB smem, 2 CTAs/SM resident.
#define SA_OFF(s) ((s) * 16384)
#define SB_OFF(s) (65536 + (s) * 8192)
#define SMEM_TOTAL 98304

__global__ __launch_bounds__(256, 2) void gemm_kernel(const float* __restrict__ wscale,
                                                      float* __restrict__ out) {
    extern __shared__ char smem[];
    const uint32_t sb = smem_to_u32(smem);
    const int tid = threadIdx.x;
    const int lane = tid & 31, wid = tid >> 5;
    const int wm = wid >> 1, wn = wid & 1;    // 4m x 2n
    const int nbase = blockIdx.x * BN;
    const int mbase = blockIdx.y * BM;
    const int kzoff = blockIdx.z * (INF / KSPLIT);   // 0 or 2048

    const int8_t* abase = g_xq + (size_t)mbase * INF + kzoff;
    const int8_t* bbase = g_w8 + (size_t)nbase * INF + kzoff;

    int acc[2][4][4];
#pragma unroll
    for (int i = 0; i < 2; i++)
#pragma unroll
        for (int j = 0; j < 4; j++)
#pragma unroll
            for (int k = 0; k < 4; k++) acc[i][j][k] = 0;

    auto issue = [&](int c, int s) {
#pragma unroll
        for (int t = 0; t < 4; t++) {
            int i = tid + t * 256;
            int r = i >> 3, cc = i & 7;
            const int8_t* src = abase + (size_t)r * INF + c * BK + cc * 16;
            uint32_t dst = sb + SA_OFF(s) + (uint32_t)(r * 128 + ((cc ^ (r & 7)) << 4));
            asm volatile("cp.async.cg.shared.global [%0], [%1], 16;" :: "r"(dst), "l"(src));
        }
#pragma unroll
        for (int t = 0; t < 2; t++) {
            int i = tid + t * 256;
            int r = i >> 3, cc = i & 7;
            const int8_t* src = bbase + (size_t)r * INF + c * BK + cc * 16;
            uint32_t dst = sb + SB_OFF(s) + (uint32_t)(r * 128 + ((cc ^ (r & 7)) << 4));
            asm volatile("cp.async.cg.shared.global [%0], [%1], 16;" :: "r"(dst), "l"(src));
        }
        asm volatile("cp.async.commit_group;" ::: "memory");
    };

    auto compute = [&](int s) {
#pragma unroll
        for (int ksl = 0; ksl < 4; ksl++) {
            uint32_t a[2][4];
#pragma unroll
            for (int mf = 0; mf < 2; mf++) {
                int row = wm * 32 + mf * 16 + (lane & 15);
                int kc = 2 * ksl + (lane >> 4);
                uint32_t ad = sb + SA_OFF(s) +
                              (uint32_t)(row * 128 + ((kc ^ (row & 7)) << 4));
                asm volatile("ldmatrix.sync.aligned.m8n8.x4.shared.b16 {%0,%1,%2,%3}, [%4];"
                    : "=r"(a[mf][0]), "=r"(a[mf][1]), "=r"(a[mf][2]), "=r"(a[mf][3])
                    : "r"(ad));
            }
            uint32_t b[2][4];
#pragma unroll
            for (int np = 0; np < 2; np++) {
                int n = wn * 32 + np * 16 + (lane & 7) + ((lane >> 4) << 3);
                int kc = 2 * ksl + ((lane >> 3) & 1);
                uint32_t bd = sb + SB_OFF(s) +
                              (uint32_t)(n * 128 + ((kc ^ (n & 7)) << 4));
                asm volatile("ldmatrix.sync.aligned.m8n8.x4.shared.b16 {%0,%1,%2,%3}, [%4];"
                    : "=r"(b[np][0]), "=r"(b[np][1]), "=r"(b[np][2]), "=r"(b[np][3])
                    : "r"(bd));
            }
#pragma unroll
            for (int mf = 0; mf < 2; mf++)
#pragma unroll
                for (int nf = 0; nf < 4; nf++) {
                    uint32_t b0 = b[nf >> 1][(nf & 1) * 2];
                    uint32_t b1 = b[nf >> 1][(nf & 1) * 2 + 1];
                    asm volatile(
                        "mma.sync.aligned.m16n8k32.row.col.s32.s8.s8.s32 "
                        "{%0,%1,%2,%3}, {%4,%5,%6,%7}, {%8,%9}, {%0,%1,%2,%3};"
                        : "+r"(acc[mf][nf][0]), "+r"(acc[mf][nf][1]),
                          "+r"(acc[mf][nf][2]), "+r"(acc[mf][nf][3])
                        : "r"(a[mf][0]), "r"(a[mf][1]), "r"(a[mf][2]), "r"(a[mf][3]),
                          "r"(b0), "r"(b1));
                }
        }
    };

    // ---- prologue: 3 stages in flight ----
    issue(0, 0);
    issue(1, 1);
    issue(2, 2);

    // ---- main loop ----
#pragma unroll 1
    for (int c = 0; c < NCH_PER; c++) {
        const int s = c & (STAGES - 1);
        asm volatile("cp.async.wait_group 2;" ::: "memory");
        __syncthreads();
        if (c + 3 < NCH_PER) issue(c + 3, (c + 3) & (STAGES - 1));
        compute(s);
    }

    // ---- epilogue: atomicAdd partial = s32 * (xs*ws/127^2) onto prefed out ----
    const float inv = 1.0f / 16129.0f;
    const int grp = lane >> 2, qid = lane & 3;
#pragma unroll
    for (int mf = 0; mf < 2; mf++) {
        const int m0 = mbase + wm * 32 + mf * 16 + grp;
        const float s0 = g_xs[m0] * inv;
        const float s1 = g_xs[m0 + 8] * inv;
#pragma unroll
        for (int nf = 0; nf < 4; nf++) {
            const int o = nbase + wn * 32 + nf * 8 + qid * 2;
            const float2 wsv = *(const float2*)(wscale + o);
            float* p0 = out + (size_t)m0 * OUTF + o;
            float* p1 = out + (size_t)(m0 + 8) * OUTF + o;
            atomicAdd(p0,     (float)acc[mf][nf][0] * (s0 * wsv.x));
            atomicAdd(p0 + 1, (float)acc[mf][nf][1] * (s0 * wsv.y));
            atomicAdd(p1,     (float)acc[mf][nf][2] * (s1 * wsv.x));
            atomicAdd(p1 + 1, (float)acc[mf][nf][3] * (s1 * wsv.y));
        }
    }
}

// ---------------- launch ----------------
extern "C" void kernel_launch(void* const* d_in, const int* in_sizes, int n_in,
                              void* d_out, int out_size) {
    const float* x    = (const float*)d_in[0];
    const int*   w    = (const int*)d_in[1];
    const float* ws   = (const float*)d_in[2];
    const int*   oidx = (const int*)d_in[3];
    const float* ow   = (const float*)d_in[4];
    const float* bias = (const float*)d_in[5];
    float* out = (float*)d_out;

    cudaFuncSetAttribute(gemm_kernel, cudaFuncAttributeMaxDynamicSharedMemorySize, SMEM_TOTAL);

    mask_init_kernel<<<INF / 256, 256>>>();
    mask_scatter_kernel<<<1, NOUT>>>(oidx);
    pack_w_kernel<<<(size_t)OUTF * INF / 2048, 256>>>(w);
    quantize_kernel<<<TOK, 256>>>(x, oidx);
    outlier_bias_kernel<<<dim3(OUTF / 128, TOK / 64), 256>>>(ow, bias, out);
    gemm_kernel<<<dim3(OUTF / BN, TOK / BM, KSPLIT), 256, SMEM_TOTAL>>>(ws, out);
}

// round 6
// speedup vs baseline: 1.2010x; 1.0302x over previous
#include <cuda_runtime.h>
#include <cuda_bf16.h>
#include <cstdint>

#define TOK   256
#define INF   4096
#define OUTF  4096
#define NOUT  32

#define BM 128
#define BN 64
#define BK 128
#define KSPLIT 2
#define NCH_PER (INF / BK / KSPLIT)   // 16 k-chunks per CTA

// A block: 128 m x 128 k int8 = 16KB, swizzled, contiguous. [mt(2)][c(32)]
// B block:  64 n x 128 k int8 =  8KB, swizzled, contiguous. [nt(64)][c(32)]
#define ABLK 16384
#define BBLK 8192

// ---------------- scratch (no cudaMalloc allowed) ----------------
__device__ __align__(128) int8_t g_xq[TOK * INF];          // A blocks (1MB)
__device__ __align__(128) int8_t g_w8[(size_t)OUTF * INF]; // B blocks (16MB)
__device__ float g_xs[TOK];
__device__ float g_xout[TOK * NOUT];

__device__ __forceinline__ uint32_t smem_to_u32(const void* p) {
    uint32_t a;
    asm("{ .reg .u64 t; cvta.to.shared.u64 t, %1; cvt.u32.u64 %0, t; }" : "=r"(a) : "l"(p));
    return a;
}

#define MBARRIER_INIT(mbar, count) \
    asm volatile("mbarrier.init.shared.b64 [%0], %1;" :: "r"((uint32_t)(mbar)), "r"((uint32_t)(count)) : "memory")
#define MBARRIER_EXPECT_TX(mbar, bytes) \
    asm volatile("mbarrier.arrive.expect_tx.shared.b64 _, [%0], %1;" :: "r"((uint32_t)(mbar)), "r"((uint32_t)(bytes)) : "memory")
#define BULK_G2S(dst, src, bytes, mbar) \
    asm volatile("cp.async.bulk.shared::cluster.global.mbarrier::complete_tx::bytes [%0], [%1], %2, [%3];" \
        :: "r"((uint32_t)(dst)), "l"(src), "r"((uint32_t)(bytes)), "r"((uint32_t)(mbar)) : "memory")

#define MBARRIER_WAIT_PARITY(mbar_smem_addr, phase_parity) do { \
    uint32_t _mbar = (uint32_t)(mbar_smem_addr); \
    uint32_t _parity = (uint32_t)(phase_parity); \
    uint32_t _done; \
    asm volatile("{\n\t.reg .pred p;\n\t" \
        "mbarrier.try_wait.parity.acquire.cta.shared::cta.b64 p, [%1], %2;\n\t" \
        "selp.b32 %0, 1, 0, p;\n\t}" : "=r"(_done) : "r"(_mbar), "r"(_parity) : "memory"); \
    if (!_done) { \
        asm volatile("{\n\t.reg .pred P1;\n\t" \
            "WAIT_LOOP_%=:\n\t" \
            "mbarrier.try_wait.parity.acquire.cta.shared::cta.b64 P1, [%0], %1, 0x989680;\n\t" \
            "@P1 bra.uni WAIT_DONE_%=;\n\t" \
            "bra.uni WAIT_LOOP_%=;\n\t" \
            "WAIT_DONE_%=:\n\t}" :: "r"(_mbar), "r"(_parity) : "memory"); \
    } \
} while (0)

// ---------------- rowwise quantize + mask fuse + outlier gather ----------------
// Writes A into blocked-swizzled layout: g_xq[(mt*32+c)*16384 + rr*128 + ((cp^(rr&7))<<4)]
__global__ __launch_bounds__(256) void quantize_kernel(const float* __restrict__ x,
                                                       const int* __restrict__ oidx) {
    const int r = blockIdx.x;
    const int tid = threadIdx.x;
    const int wid = tid >> 5, lid = tid & 31;
    __shared__ int   s_oi[NOUT];
    __shared__ float red[8];
    __shared__ float s_scale;

    if (tid < NOUT) s_oi[tid] = oidx[tid];
    __syncthreads();

    const float4* xr = (const float4*)(x + (size_t)r * INF);
    float4 f[4];
#pragma unroll
    for (int t = 0; t < 4; t++) f[t] = xr[tid * 4 + t];

    // mask outliers within this thread's 16 contiguous elems
    const int kbase = tid * 16;
    unsigned mz = 0;
#pragma unroll
    for (int j = 0; j < NOUT; j++) {
        unsigned d = (unsigned)(s_oi[j] - kbase);
        if (d < 16u) mz |= 1u << d;
    }
#pragma unroll
    for (int t = 0; t < 4; t++) {
        if (mz & (1u << (t * 4 + 0))) f[t].x = 0.0f;
        if (mz & (1u << (t * 4 + 1))) f[t].y = 0.0f;
        if (mz & (1u << (t * 4 + 2))) f[t].z = 0.0f;
        if (mz & (1u << (t * 4 + 3))) f[t].w = 0.0f;
    }

    float mx = 0.0f;
#pragma unroll
    for (int t = 0; t < 4; t++)
        mx = fmaxf(mx, fmaxf(fmaxf(fabsf(f[t].x), fabsf(f[t].y)),
                             fmaxf(fabsf(f[t].z), fabsf(f[t].w))));
#pragma unroll
    for (int d = 16; d > 0; d >>= 1) mx = fmaxf(mx, __shfl_xor_sync(0xFFFFFFFFu, mx, d));
    if (lid == 0) red[wid] = mx;
    __syncthreads();
    if (tid == 0) {
        float m = red[0];
#pragma unroll
        for (int i = 1; i < 8; i++) m = fmaxf(m, red[i]);
        s_scale = m;
        g_xs[r] = m;
    }
    __syncthreads();
    const float r127 = 127.0f / fmaxf(s_scale, 1e-8f);

    uint32_t pk[4];
#pragma unroll
    for (int t = 0; t < 4; t++) {
        int q0 = min(max(__float2int_rn(f[t].x * r127), -127), 127);
        int q1 = min(max(__float2int_rn(f[t].y * r127), -127), 127);
        int q2 = min(max(__float2int_rn(f[t].z * r127), -127), 127);
        int q3 = min(max(__float2int_rn(f[t].w * r127), -127), 127);
        uint32_t p0 = __byte_perm((uint32_t)q0, (uint32_t)q1, 0x0040);
        uint32_t p1 = __byte_perm((uint32_t)q2, (uint32_t)q3, 0x0040);
        pk[t] = __byte_perm(p0, p1, 0x5410);
    }
    const int mt = r >> 7, rr = r & 127;
    const int c = tid >> 3, cp = tid & 7;
    int8_t* dst = g_xq + ((size_t)(mt * 32 + c) << 14) + rr * 128 + (((cp ^ (rr & 7))) << 4);
    *(uint4*)dst = make_uint4(pk[0], pk[1], pk[2], pk[3]);

    if (tid < NOUT) {
        g_xout[r * NOUT + tid] = x[(size_t)r * INF + s_oi[tid]];
    }
}

// ---------------- prepack: w int32 -> blocked-swizzled int8 ----------------
// block (nt, c): 64 o-rows x 128 k -> 8KB at g_w8 + (nt*32+c)*8192
__global__ __launch_bounds__(256) void pack_w_kernel(const int* __restrict__ w) {
    const int nt = blockIdx.x >> 5, c = blockIdx.x & 31;
    const int tid = threadIdx.x;
#pragma unroll
    for (int t = 0; t < 2; t++) {
        int u = tid + t * 256;           // [0,512): r = u>>3, cc = u&7
        int r = u >> 3, cc = u & 7;
        const int* src = w + (size_t)(nt * 64 + r) * INF + c * 128 + cc * 16;
        int4 v0 = *(const int4*)(src);
        int4 v1 = *(const int4*)(src + 4);
        int4 v2 = *(const int4*)(src + 8);
        int4 v3 = *(const int4*)(src + 12);
        uint32_t a0 = __byte_perm(__byte_perm((uint32_t)v0.x, (uint32_t)v0.y, 0x0040),
                                  __byte_perm((uint32_t)v0.z, (uint32_t)v0.w, 0x0040), 0x5410);
        uint32_t a1 = __byte_perm(__byte_perm((uint32_t)v1.x, (uint32_t)v1.y, 0x0040),
                                  __byte_perm((uint32_t)v1.z, (uint32_t)v1.w, 0x0040), 0x5410);
        uint32_t a2 = __byte_perm(__byte_perm((uint32_t)v2.x, (uint32_t)v2.y, 0x0040),
                                  __byte_perm((uint32_t)v2.z, (uint32_t)v2.w, 0x0040), 0x5410);
        uint32_t a3 = __byte_perm(__byte_perm((uint32_t)v3.x, (uint32_t)v3.y, 0x0040),
                                  __byte_perm((uint32_t)v3.z, (uint32_t)v3.w, 0x0040), 0x5410);
        int8_t* dst = g_w8 + ((size_t)(nt * 32 + c) << 13) + r * 128 + ((cc ^ (r & 7)) << 4);
        *(uint4*)dst = make_uint4(a0, a1, a2, a3);
    }
}

// ---------------- outlier GEMM + bias -> out (prefill) ----------------
// grid (32 o-tiles of 128, 8 t-tiles of 32), 256 thr
__global__ __launch_bounds__(256) void outlier_bias_kernel(const float* __restrict__ ow,
                                                           const float* __restrict__ bias,
                                                           float* __restrict__ out) {
    __shared__ float s_owT[NOUT * 128];  // [j][o]
    __shared__ float s_x[32 * NOUT];     // [t][j]
    __shared__ float s_b[128];

    const int tid = threadIdx.x;
    const int obase = blockIdx.x * 128;
    const int tbase = blockIdx.y * 32;

    if (tid < 128) s_b[tid] = bias[obase + tid];

#pragma unroll
    for (int t = 0; t < 4; t++) {
        int i = tid + t * 256;               // float4 index in [0,1024)
        int o = i >> 3, j4 = i & 7;
        float4 f = ((const float4*)ow)[(size_t)obase * 8 + i];
        s_owT[(j4 * 4 + 0) * 128 + o] = f.x;
        s_owT[(j4 * 4 + 1) * 128 + o] = f.y;
        s_owT[(j4 * 4 + 2) * 128 + o] = f.z;
        s_owT[(j4 * 4 + 3) * 128 + o] = f.w;
    }
    ((float4*)s_x)[tid] = ((const float4*)(g_xout + tbase * NOUT))[tid];
    __syncthreads();

    const int ty = tid >> 5, tx = tid & 31;  // 8 groups x 4 t-rows, 4 o-cols
    float acc[4][4];
#pragma unroll
    for (int tt = 0; tt < 4; tt++)
#pragma unroll
        for (int c = 0; c < 4; c++) acc[tt][c] = s_b[tx + c * 32];

#pragma unroll
    for (int j = 0; j < NOUT; j++) {
        float wv[4];
#pragma unroll
        for (int c = 0; c < 4; c++) wv[c] = s_owT[j * 128 + tx + c * 32];
#pragma unroll
        for (int tt = 0; tt < 4; tt++) {
            float xv = s_x[(ty * 4 + tt) * NOUT + j];
#pragma unroll
            for (int c = 0; c < 4; c++) acc[tt][c] += xv * wv[c];
        }
    }
#pragma unroll
    for (int tt = 0; tt < 4; tt++)
#pragma unroll
        for (int c = 0; c < 4; c++)
            out[(size_t)(tbase + ty * 4 + tt) * OUTF + obase + tx + c * 32] = acc[tt][c];
}

// ---------------- int8 GEMM: bulk-copy (TMA) pipeline, mma.sync core ----------------
// CTA 128x64, 8 warps (4m x 2n), warp tile 32x32. 3-stage pipeline, 72KB smem.
#define SA_OFF(s) ((s) * 24576)
#define SB_OFF(s) ((s) * 24576 + 16384)
#define MB_OFF    73728
#define SMEM_TOTAL (73728 + 128)

__global__ __launch_bounds__(256, 2) void gemm_kernel(const float* __restrict__ wscale,
                                                      float* __restrict__ out) {
    extern __shared__ char smem[];
    const uint32_t sb = smem_to_u32(smem);
    const int tid = threadIdx.x;
    const int lane = tid & 31, wid = tid >> 5;
    const int wm = wid >> 1, wn = wid & 1;    // 4m x 2n
    const int nt = blockIdx.x;                // 64 n-tiles
    const int mt = blockIdx.y;                // 2 m-tiles
    const int kz = blockIdx.z;                // 2 k-splits

    const int8_t* Asrc = g_xq + ((size_t)(mt * 32 + kz * NCH_PER) << 14);
    const int8_t* Bsrc = g_w8 + ((size_t)(nt * 32 + kz * NCH_PER) << 13);

    if (tid == 0) {
#pragma unroll
        for (int s = 0; s < 3; s++) MBARRIER_INIT(sb + MB_OFF + s * 8, 1);
    }
    __syncthreads();

    // prologue: fill stages 0..2
    if (tid == 0) {
#pragma unroll
        for (int s = 0; s < 3; s++) {
            const uint32_t mb = sb + MB_OFF + s * 8;
            MBARRIER_EXPECT_TX(mb, ABLK + BBLK);
            BULK_G2S(sb + SA_OFF(s), Asrc + (size_t)s * ABLK, ABLK, mb);
            BULK_G2S(sb + SB_OFF(s), Bsrc + (size_t)s * BBLK, BBLK, mb);
        }
    }

    int acc[2][4][4];
#pragma unroll
    for (int i = 0; i < 2; i++)
#pragma unroll
        for (int j = 0; j < 4; j++)
#pragma unroll
            for (int k = 0; k < 4; k++) acc[i][j][k] = 0;

#pragma unroll 1
    for (int c = 0; c < NCH_PER; c++) {
        const int s = c % 3;
        const int ph = (c / 3) & 1;
        MBARRIER_WAIT_PARITY(sb + MB_OFF + s * 8, ph);

        // ---- compute on stage s (identical to proven R5 core) ----
#pragma unroll
        for (int ksl = 0; ksl < 4; ksl++) {
            uint32_t a[2][4];
#pragma unroll
            for (int mf = 0; mf < 2; mf++) {
                int row = wm * 32 + mf * 16 + (lane & 15);
                int kc = 2 * ksl + (lane >> 4);
                uint32_t ad = sb + SA_OFF(s) +
                              (uint32_t)(row * 128 + ((kc ^ (row & 7)) << 4));
                asm volatile("ldmatrix.sync.aligned.m8n8.x4.shared.b16 {%0,%1,%2,%3}, [%4];"
                    : "=r"(a[mf][0]), "=r"(a[mf][1]), "=r"(a[mf][2]), "=r"(a[mf][3])
                    : "r"(ad));
            }
            uint32_t b[2][4];
#pragma unroll
            for (int np = 0; np < 2; np++) {
                int n = wn * 32 + np * 16 + (lane & 7) + ((lane >> 4) << 3);
                int kc = 2 * ksl + ((lane >> 3) & 1);
                uint32_t bd = sb + SB_OFF(s) +
                              (uint32_t)(n * 128 + ((kc ^ (n & 7)) << 4));
                asm volatile("ldmatrix.sync.aligned.m8n8.x4.shared.b16 {%0,%1,%2,%3}, [%4];"
                    : "=r"(b[np][0]), "=r"(b[np][1]), "=r"(b[np][2]), "=r"(b[np][3])
                    : "r"(bd));
            }
#pragma unroll
            for (int mf = 0; mf < 2; mf++)
#pragma unroll
                for (int nf = 0; nf < 4; nf++) {
                    uint32_t b0 = b[nf >> 1][(nf & 1) * 2];
                    uint32_t b1 = b[nf >> 1][(nf & 1) * 2 + 1];
                    asm volatile(
                        "mma.sync.aligned.m16n8k32.row.col.s32.s8.s8.s32 "
                        "{%0,%1,%2,%3}, {%4,%5,%6,%7}, {%8,%9}, {%0,%1,%2,%3};"
                        : "+r"(acc[mf][nf][0]), "+r"(acc[mf][nf][1]),
                          "+r"(acc[mf][nf][2]), "+r"(acc[mf][nf][3])
                        : "r"(a[mf][0]), "r"(a[mf][1]), "r"(a[mf][2]), "r"(a[mf][3]),
                          "r"(b0), "r"(b1));
                }
        }

        __syncthreads();  // all warps done reading stage s
        if (tid == 0 && c + 3 < NCH_PER) {
            const uint32_t mb = sb + MB_OFF + s * 8;
            MBARRIER_EXPECT_TX(mb, ABLK + BBLK);
            BULK_G2S(sb + SA_OFF(s), Asrc + (size_t)(c + 3) * ABLK, ABLK, mb);
            BULK_G2S(sb + SB_OFF(s), Bsrc + (size_t)(c + 3) * BBLK, BBLK, mb);
        }
    }

    // ---- epilogue: atomicAdd partial = s32 * (xs*ws/127^2) onto prefilled out ----
    const float inv = 1.0f / 16129.0f;
    const int grp = lane >> 2, qid = lane & 3;
    const int nbase = nt * BN, mbase = mt * BM;
#pragma unroll
    for (int mf = 0; mf < 2; mf++) {
        const int m0 = mbase + wm * 32 + mf * 16 + grp;
        const float s0 = g_xs[m0] * inv;
        const float s1 = g_xs[m0 + 8] * inv;
#pragma unroll
        for (int nf = 0; nf < 4; nf++) {
            const int o = nbase + wn * 32 + nf * 8 + qid * 2;
            const float2 wsv = *(const float2*)(wscale + o);
            float* p0 = out + (size_t)m0 * OUTF + o;
            float* p1 = out + (size_t)(m0 + 8) * OUTF + o;
            atomicAdd(p0,     (float)acc[mf][nf][0] * (s0 * wsv.x));
            atomicAdd(p0 + 1, (float)acc[mf][nf][1] * (s0 * wsv.y));
            atomicAdd(p1,     (float)acc[mf][nf][2] * (s1 * wsv.x));
            atomicAdd(p1 + 1, (float)acc[mf][nf][3] * (s1 * wsv.y));
        }
    }
}

// ---------------- launch ----------------
extern "C" void kernel_launch(void* const* d_in, const int* in_sizes, int n_in,
                              void* d_out, int out_size) {
    const float* x    = (const float*)d_in[0];
    const int*   w    = (const int*)d_in[1];
    const float* ws   = (const float*)d_in[2];
    const int*   oidx = (const int*)d_in[3];
    const float* ow   = (const float*)d_in[4];
    const float* bias = (const float*)d_in[5];
    float* out = (float*)d_out;

    cudaFuncSetAttribute(gemm_kernel, cudaFuncAttributeMaxDynamicSharedMemorySize, SMEM_TOTAL);

    quantize_kernel<<<TOK, 256>>>(x, oidx);
    pack_w_kernel<<<64 * 32, 256>>>(w);
    outlier_bias_kernel<<<dim3(OUTF / 128, TOK / 32), 256>>>(ow, bias, out);
    gemm_kernel<<<dim3(OUTF / BN, TOK / BM, KSPLIT), 256, SMEM_TOTAL>>>(ws, out);
}

// round 7
// speedup vs baseline: 1.2048x; 1.0031x over previous
#include <cuda_runtime.h>
#include <cuda_bf16.h>
#include <cstdint>

#define TOK   256
#define INF   4096
#define OUTF  4096
#define NOUT  32

#define BM 128
#define BN 64
#define BK 128
#define KSPLIT 4
#define NCH_PER (INF / BK / KSPLIT)   // 8 k-chunks per CTA
#define STAGES 4

// A block: 128 m x 128 k int8 = 16KB, swizzled, contiguous. [mt(2)][c(32)]
// B block:  64 n x 128 k int8 =  8KB, swizzled, contiguous. [nt(64)][c(32)]
#define ABLK 16384
#define BBLK 8192

// ---------------- scratch (no cudaMalloc allowed) ----------------
__device__ __align__(128) int8_t g_xq[TOK * INF];          // A blocks (1MB)
__device__ __align__(128) int8_t g_w8[(size_t)OUTF * INF]; // B blocks (16MB)
__device__ float g_xs[TOK];
__device__ float g_xout[TOK * NOUT];

__device__ __forceinline__ uint32_t smem_to_u32(const void* p) {
    uint32_t a;
    asm("{ .reg .u64 t; cvta.to.shared.u64 t, %1; cvt.u32.u64 %0, t; }" : "=r"(a) : "l"(p));
    return a;
}

#define MBARRIER_INIT(mbar, count) \
    asm volatile("mbarrier.init.shared.b64 [%0], %1;" :: "r"((uint32_t)(mbar)), "r"((uint32_t)(count)) : "memory")
#define MBARRIER_EXPECT_TX(mbar, bytes) \
    asm volatile("mbarrier.arrive.expect_tx.shared.b64 _, [%0], %1;" :: "r"((uint32_t)(mbar)), "r"((uint32_t)(bytes)) : "memory")
#define BULK_G2S(dst, src, bytes, mbar) \
    asm volatile("cp.async.bulk.shared::cluster.global.mbarrier::complete_tx::bytes [%0], [%1], %2, [%3];" \
        :: "r"((uint32_t)(dst)), "l"(src), "r"((uint32_t)(bytes)), "r"((uint32_t)(mbar)) : "memory")

#define MBARRIER_WAIT_PARITY(mbar_smem_addr, phase_parity) do { \
    uint32_t _mbar = (uint32_t)(mbar_smem_addr); \
    uint32_t _parity = (uint32_t)(phase_parity); \
    uint32_t _done; \
    asm volatile("{\n\t.reg .pred p;\n\t" \
        "mbarrier.try_wait.parity.acquire.cta.shared::cta.b64 p, [%1], %2;\n\t" \
        "selp.b32 %0, 1, 0, p;\n\t}" : "=r"(_done) : "r"(_mbar), "r"(_parity) : "memory"); \
    if (!_done) { \
        asm volatile("{\n\t.reg .pred P1;\n\t" \
            "WAIT_LOOP_%=:\n\t" \
            "mbarrier.try_wait.parity.acquire.cta.shared::cta.b64 P1, [%0], %1, 0x989680;\n\t" \
            "@P1 bra.uni WAIT_DONE_%=;\n\t" \
            "bra.uni WAIT_LOOP_%=;\n\t" \
            "WAIT_DONE_%=:\n\t}" :: "r"(_mbar), "r"(_parity) : "memory"); \
    } \
} while (0)

// ---------------- rowwise quantize + mask fuse + outlier gather ----------------
__global__ __launch_bounds__(256) void quantize_kernel(const float* __restrict__ x,
                                                       const int* __restrict__ oidx) {
    const int r = blockIdx.x;
    const int tid = threadIdx.x;
    const int wid = tid >> 5, lid = tid & 31;
    __shared__ int   s_oi[NOUT];
    __shared__ float red[8];
    __shared__ float s_scale;

    // issue x loads FIRST (critical-path LDGs), then oidx
    const float4* xr = (const float4*)(x + (size_t)r * INF);
    float4 f[4];
#pragma unroll
    for (int t = 0; t < 4; t++) f[t] = xr[tid * 4 + t];

    if (tid < NOUT) s_oi[tid] = oidx[tid];
    __syncthreads();

    // mask outliers within this thread's 16 contiguous elems
    const int kbase = tid * 16;
    unsigned mz = 0;
#pragma unroll
    for (int j = 0; j < NOUT; j++) {
        unsigned d = (unsigned)(s_oi[j] - kbase);
        if (d < 16u) mz |= 1u << d;
    }
#pragma unroll
    for (int t = 0; t < 4; t++) {
        if (mz & (1u << (t * 4 + 0))) f[t].x = 0.0f;
        if (mz & (1u << (t * 4 + 1))) f[t].y = 0.0f;
        if (mz & (1u << (t * 4 + 2))) f[t].z = 0.0f;
        if (mz & (1u << (t * 4 + 3))) f[t].w = 0.0f;
    }

    float mx = 0.0f;
#pragma unroll
    for (int t = 0; t < 4; t++)
        mx = fmaxf(mx, fmaxf(fmaxf(fabsf(f[t].x), fabsf(f[t].y)),
                             fmaxf(fabsf(f[t].z), fabsf(f[t].w))));
#pragma unroll
    for (int d = 16; d > 0; d >>= 1) mx = fmaxf(mx, __shfl_xor_sync(0xFFFFFFFFu, mx, d));
    if (lid == 0) red[wid] = mx;
    __syncthreads();
    if (tid == 0) {
        float m = red[0];
#pragma unroll
        for (int i = 1; i < 8; i++) m = fmaxf(m, red[i]);
        s_scale = m;
        g_xs[r] = m;
    }
    __syncthreads();
    const float r127 = 127.0f / fmaxf(s_scale, 1e-8f);

    uint32_t pk[4];
#pragma unroll
    for (int t = 0; t < 4; t++) {
        int q0 = min(max(__float2int_rn(f[t].x * r127), -127), 127);
        int q1 = min(max(__float2int_rn(f[t].y * r127), -127), 127);
        int q2 = min(max(__float2int_rn(f[t].z * r127), -127), 127);
        int q3 = min(max(__float2int_rn(f[t].w * r127), -127), 127);
        uint32_t p0 = __byte_perm((uint32_t)q0, (uint32_t)q1, 0x0040);
        uint32_t p1 = __byte_perm((uint32_t)q2, (uint32_t)q3, 0x0040);
        pk[t] = __byte_perm(p0, p1, 0x5410);
    }
    const int mt = r >> 7, rr = r & 127;
    const int c = tid >> 3, cp = tid & 7;
    int8_t* dst = g_xq + ((size_t)(mt * 32 + c) << 14) + rr * 128 + (((cp ^ (rr & 7))) << 4);
    *(uint4*)dst = make_uint4(pk[0], pk[1], pk[2], pk[3]);

    if (tid < NOUT) {
        g_xout[r * NOUT + tid] = x[(size_t)r * INF + s_oi[tid]];
    }
}

// ---------------- prepack: w int32 -> blocked-swizzled int8 ----------------
__global__ __launch_bounds__(256) void pack_w_kernel(const int* __restrict__ w) {
    const int nt = blockIdx.x >> 5, c = blockIdx.x & 31;
    const int tid = threadIdx.x;
#pragma unroll
    for (int t = 0; t < 2; t++) {
        int u = tid + t * 256;           // [0,512): r = u>>3, cc = u&7
        int r = u >> 3, cc = u & 7;
        const int* src = w + (size_t)(nt * 64 + r) * INF + c * 128 + cc * 16;
        int4 v0 = *(const int4*)(src);
        int4 v1 = *(const int4*)(src + 4);
        int4 v2 = *(const int4*)(src + 8);
        int4 v3 = *(const int4*)(src + 12);
        uint32_t a0 = __byte_perm(__byte_perm((uint32_t)v0.x, (uint32_t)v0.y, 0x0040),
                                  __byte_perm((uint32_t)v0.z, (uint32_t)v0.w, 0x0040), 0x5410);
        uint32_t a1 = __byte_perm(__byte_perm((uint32_t)v1.x, (uint32_t)v1.y, 0x0040),
                                  __byte_perm((uint32_t)v1.z, (uint32_t)v1.w, 0x0040), 0x5410);
        uint32_t a2 = __byte_perm(__byte_perm((uint32_t)v2.x, (uint32_t)v2.y, 0x0040),
                                  __byte_perm((uint32_t)v2.z, (uint32_t)v2.w, 0x0040), 0x5410);
        uint32_t a3 = __byte_perm(__byte_perm((uint32_t)v3.x, (uint32_t)v3.y, 0x0040),
                                  __byte_perm((uint32_t)v3.z, (uint32_t)v3.w, 0x0040), 0x5410);
        int8_t* dst = g_w8 + ((size_t)(nt * 32 + c) << 13) + r * 128 + ((cc ^ (r & 7)) << 4);
        *(uint4*)dst = make_uint4(a0, a1, a2, a3);
    }
}

// ---------------- outlier GEMM + bias -> out (prefill) ----------------
__global__ __launch_bounds__(256) void outlier_bias_kernel(const float* __restrict__ ow,
                                                           const float* __restrict__ bias,
                                                           float* __restrict__ out) {
    __shared__ float s_owT[NOUT * 128];  // [j][o]
    __shared__ float s_x[32 * NOUT];     // [t][j]
    __shared__ float s_b[128];

    const int tid = threadIdx.x;
    const int obase = blockIdx.x * 128;
    const int tbase = blockIdx.y * 32;

    if (tid < 128) s_b[tid] = bias[obase + tid];

#pragma unroll
    for (int t = 0; t < 4; t++) {
        int i = tid + t * 256;               // float4 index in [0,1024)
        int o = i >> 3, j4 = i & 7;
        float4 f = ((const float4*)ow)[(size_t)obase * 8 + i];
        s_owT[(j4 * 4 + 0) * 128 + o] = f.x;
        s_owT[(j4 * 4 + 1) * 128 + o] = f.y;
        s_owT[(j4 * 4 + 2) * 128 + o] = f.z;
        s_owT[(j4 * 4 + 3) * 128 + o] = f.w;
    }
    ((float4*)s_x)[tid] = ((const float4*)(g_xout + tbase * NOUT))[tid];
    __syncthreads();

    const int ty = tid >> 5, tx = tid & 31;
    float acc[4][4];
#pragma unroll
    for (int tt = 0; tt < 4; tt++)
#pragma unroll
        for (int c = 0; c < 4; c++) acc[tt][c] = s_b[tx + c * 32];

#pragma unroll
    for (int j = 0; j < NOUT; j++) {
        float wv[4];
#pragma unroll
        for (int c = 0; c < 4; c++) wv[c] = s_owT[j * 128 + tx + c * 32];
#pragma unroll
        for (int tt = 0; tt < 4; tt++) {
            float xv = s_x[(ty * 4 + tt) * NOUT + j];
#pragma unroll
            for (int c = 0; c < 4; c++) acc[tt][c] += xv * wv[c];
        }
    }
#pragma unroll
    for (int tt = 0; tt < 4; tt++)
#pragma unroll
        for (int c = 0; c < 4; c++)
            out[(size_t)(tbase + ty * 4 + tt) * OUTF + obase + tx + c * 32] = acc[tt][c];
}

// ---------------- int8 GEMM: 4-stage bulk pipeline w/ early refill ----------------
// CTA 128x64, 8 warps (4m x 2n), warp tile 32x32. 96KB smem, 2 CTAs/SM.
#define SA_OFF(s) ((s) * 24576)
#define SB_OFF(s) ((s) * 24576 + 16384)
#define MB_OFF    98304
#define SMEM_TOTAL (98304 + 128)

__global__ __launch_bounds__(256, 2) void gemm_kernel(const float* __restrict__ wscale,
                                                      float* __restrict__ out) {
    extern __shared__ char smem[];
    const uint32_t sb = smem_to_u32(smem);
    const int tid = threadIdx.x;
    const int lane = tid & 31, wid = tid >> 5;
    const int wm = wid >> 1, wn = wid & 1;    // 4m x 2n
    const int nt = blockIdx.x;                // 64 n-tiles
    const int mt = blockIdx.y;                // 2 m-tiles
    const int kz = blockIdx.z;                // 4 k-splits

    const int8_t* Asrc = g_xq + ((size_t)(mt * 32 + kz * NCH_PER) << 14);
    const int8_t* Bsrc = g_w8 + ((size_t)(nt * 32 + kz * NCH_PER) << 13);

    if (tid == 0) {
#pragma unroll
        for (int s = 0; s < STAGES; s++) MBARRIER_INIT(sb + MB_OFF + s * 8, 1);
    }
    __syncthreads();

    // prologue: fill stages 0..2 (chunks 0..2)
    if (tid == 0) {
#pragma unroll
        for (int s = 0; s < 3; s++) {
            const uint32_t mb = sb + MB_OFF + s * 8;
            MBARRIER_EXPECT_TX(mb, ABLK + BBLK);
            BULK_G2S(sb + SA_OFF(s), Asrc + (size_t)s * ABLK, ABLK, mb);
            BULK_G2S(sb + SB_OFF(s), Bsrc + (size_t)s * BBLK, BBLK, mb);
        }
    }

    int acc[2][4][4];
#pragma unroll
    for (int i = 0; i < 2; i++)
#pragma unroll
        for (int j = 0; j < 4; j++)
#pragma unroll
            for (int k = 0; k < 4; k++) acc[i][j][k] = 0;

#pragma unroll 1
    for (int c = 0; c < NCH_PER; c++) {
        const int s = c & (STAGES - 1);
        const int ph = (c >> 2) & 1;
        MBARRIER_WAIT_PARITY(sb + MB_OFF + s * 8, ph);

        // early refill: stage (c+3)&3 == (c-1)&3 was freed by last iter's syncthreads
        if (tid == 0 && c + 3 < NCH_PER) {
            const int fs = (c + 3) & (STAGES - 1);
            const uint32_t mb = sb + MB_OFF + fs * 8;
            MBARRIER_EXPECT_TX(mb, ABLK + BBLK);
            BULK_G2S(sb + SA_OFF(fs), Asrc + (size_t)(c + 3) * ABLK, ABLK, mb);
            BULK_G2S(sb + SB_OFF(fs), Bsrc + (size_t)(c + 3) * BBLK, BBLK, mb);
        }

        // ---- compute on stage s (proven core) ----
#pragma unroll
        for (int ksl = 0; ksl < 4; ksl++) {
            uint32_t a[2][4];
#pragma unroll
            for (int mf = 0; mf < 2; mf++) {
                int row = wm * 32 + mf * 16 + (lane & 15);
                int kc = 2 * ksl + (lane >> 4);
                uint32_t ad = sb + SA_OFF(s) +
                              (uint32_t)(row * 128 + ((kc ^ (row & 7)) << 4));
                asm volatile("ldmatrix.sync.aligned.m8n8.x4.shared.b16 {%0,%1,%2,%3}, [%4];"
                    : "=r"(a[mf][0]), "=r"(a[mf][1]), "=r"(a[mf][2]), "=r"(a[mf][3])
                    : "r"(ad));
            }
            uint32_t b[2][4];
#pragma unroll
            for (int np = 0; np < 2; np++) {
                int n = wn * 32 + np * 16 + (lane & 7) + ((lane >> 4) << 3);
                int kc = 2 * ksl + ((lane >> 3) & 1);
                uint32_t bd = sb + SB_OFF(s) +
                              (uint32_t)(n * 128 + ((kc ^ (n & 7)) << 4));
                asm volatile("ldmatrix.sync.aligned.m8n8.x4.shared.b16 {%0,%1,%2,%3}, [%4];"
                    : "=r"(b[np][0]), "=r"(b[np][1]), "=r"(b[np][2]), "=r"(b[np][3])
                    : "r"(bd));
            }
#pragma unroll
            for (int mf = 0; mf < 2; mf++)
#pragma unroll
                for (int nf = 0; nf < 4; nf++) {
                    uint32_t b0 = b[nf >> 1][(nf & 1) * 2];
                    uint32_t b1 = b[nf >> 1][(nf & 1) * 2 + 1];
                    asm volatile(
                        "mma.sync.aligned.m16n8k32.row.col.s32.s8.s8.s32 "
                        "{%0,%1,%2,%3}, {%4,%5,%6,%7}, {%8,%9}, {%0,%1,%2,%3};"
                        : "+r"(acc[mf][nf][0]), "+r"(acc[mf][nf][1]),
                          "+r"(acc[mf][nf][2]), "+r"(acc[mf][nf][3])
                        : "r"(a[mf][0]), "r"(a[mf][1]), "r"(a[mf][2]), "r"(a[mf][3]),
                          "r"(b0), "r"(b1));
                }
        }
        __syncthreads();  // all warps done with stage s -> refillable next iter
    }

    // ---- epilogue: atomicAdd partial = s32 * (xs*ws/127^2) onto prefilled out ----
    const float inv = 1.0f / 16129.0f;
    const int grp = lane >> 2, qid = lane & 3;
    const int nbase = nt * BN, mbase = mt * BM;
#pragma unroll
    for (int mf = 0; mf < 2; mf++) {
        const int m0 = mbase + wm * 32 + mf * 16 + grp;
        const float s0 = g_xs[m0] * inv;
        const float s1 = g_xs[m0 + 8] * inv;
#pragma unroll
        for (int nf = 0; nf < 4; nf++) {
            const int o = nbase + wn * 32 + nf * 8 + qid * 2;
            const float2 wsv = *(const float2*)(wscale + o);
            float* p0 = out + (size_t)m0 * OUTF + o;
            float* p1 = out + (size_t)(m0 + 8) * OUTF + o;
            atomicAdd(p0,     (float)acc[mf][nf][0] * (s0 * wsv.x));
            atomicAdd(p0 + 1, (float)acc[mf][nf][1] * (s0 * wsv.y));
            atomicAdd(p1,     (float)acc[mf][nf][2] * (s1 * wsv.x));
            atomicAdd(p1 + 1, (float)acc[mf][nf][3] * (s1 * wsv.y));
        }
    }
}

// ---------------- launch: fork-join streams so pre-kernels overlap ----------------
extern "C" void kernel_launch(void* const* d_in, const int* in_sizes, int n_in,
                              void* d_out, int out_size) {
    const float* x    = (const float*)d_in[0];
    const int*   w    = (const int*)d_in[1];
    const float* ws   = (const float*)d_in[2];
    const int*   oidx = (const int*)d_in[3];
    const float* ow   = (const float*)d_in[4];
    const float* bias = (const float*)d_in[5];
    float* out = (float*)d_out;

    static cudaStream_t s1 = nullptr, s2 = nullptr;
    static cudaEvent_t e0 = nullptr, e1 = nullptr, e2 = nullptr;
    if (s1 == nullptr) {
        cudaStreamCreateWithFlags(&s1, cudaStreamNonBlocking);
        cudaStreamCreateWithFlags(&s2, cudaStreamNonBlocking);
        cudaEventCreateWithFlags(&e0, cudaEventDisableTiming);
        cudaEventCreateWithFlags(&e1, cudaEventDisableTiming);
        cudaEventCreateWithFlags(&e2, cudaEventDisableTiming);
        cudaFuncSetAttribute(gemm_kernel, cudaFuncAttributeMaxDynamicSharedMemorySize, SMEM_TOTAL);
    }

    // fork
    cudaEventRecord(e0, 0);
    cudaStreamWaitEvent(s1, e0, 0);
    cudaStreamWaitEvent(s2, e0, 0);

    pack_w_kernel<<<64 * 32, 256, 0, s1>>>(w);
    quantize_kernel<<<TOK, 256, 0, s2>>>(x, oidx);
    outlier_bias_kernel<<<dim3(OUTF / 128, TOK / 32), 256, 0, s2>>>(ow, bias, out);

    // join
    cudaEventRecord(e1, s1);
    cudaEventRecord(e2, s2);
    cudaStreamWaitEvent(0, e1, 0);
    cudaStreamWaitEvent(0, e2, 0);

    gemm_kernel<<<dim3(OUTF / BN, TOK / BM, KSPLIT), 256, SMEM_TOTAL>>>(ws, out);
}